// round 2
// baseline (speedup 1.0000x reference)
#include <cuda_runtime.h>

#define NB   4
#define NN   50000
#define FIN  32
#define H2   30
#define BN   (NB*NN)       // 200000 node-batch rows
#define BD   128           // edge-kernel block size

// Static scratch (no allocations allowed).
__device__ __align__(128) float g_YA[(size_t)BN*32];   // x @ W1[0:32]
__device__ __align__(128) float g_YB[(size_t)BN*32];   // x @ W1[32:64] + b1
__device__ __align__(128) float g_SC[(size_t)BN*32];   // padded 30->32 accumulator
__device__ double g_sum, g_sumsq;
__device__ float  g_mean, g_istd;
__device__ int    g_is64;

__device__ __forceinline__ float sigmoidf(float x){
    return __fdividef(1.0f, 1.0f + __expf(-x));
}

__device__ __forceinline__ void red_add_v4(float* p, float a, float b, float c, float d){
    asm volatile("red.global.add.v4.f32 [%0], {%1,%2,%3,%4};"
                 :: "l"(p), "f"(a), "f"(b), "f"(c), "f"(d) : "memory");
}

// ---------------- K0: zero scratch + accumulators + dtype probe ----------------
// Probe: view edge_index as int32. int64 values in [0,50000) have zero high
// words at every odd int32 position; int32 random indices almost surely don't.
// Reads only the first 512 int32 (2 KB) — in-bounds under either dtype.
__global__ void k_zero(const int* __restrict__ ei32){
    size_t n4 = (size_t)BN*32/4;
    float4 z = make_float4(0.f,0.f,0.f,0.f);
    float4* p = (float4*)g_SC;
    for (size_t i = (size_t)blockIdx.x*blockDim.x + threadIdx.x; i < n4;
         i += (size_t)gridDim.x*blockDim.x) p[i] = z;
    if (blockIdx.x==0 && threadIdx.x==0){
        g_sum = 0.0; g_sumsq = 0.0;
        int all_hi_zero = 1;
        for (int k = 1; k < 512; k += 2) all_hi_zero &= (ei32[k] == 0);
        g_is64 = all_hi_zero;
    }
}

// ---------------- KA: edge_attr sum / sumsq ----------------
__global__ void k_stats(const float* __restrict__ ea, int E){
    float s = 0.f, s2 = 0.f;
    for (int i = blockIdx.x*blockDim.x + threadIdx.x; i < E; i += gridDim.x*blockDim.x){
        float v = ea[i]; s += v; s2 = fmaf(v, v, s2);
    }
    #pragma unroll
    for (int o = 16; o; o >>= 1){
        s  += __shfl_down_sync(0xffffffffu, s,  o);
        s2 += __shfl_down_sync(0xffffffffu, s2, o);
    }
    __shared__ float ws[32], ws2[32];
    int lane = threadIdx.x & 31, w = threadIdx.x >> 5;
    if (lane == 0){ ws[w] = s; ws2[w] = s2; }
    __syncthreads();
    if (w == 0){
        int nw = blockDim.x >> 5;
        s  = (lane < nw) ? ws[lane]  : 0.f;
        s2 = (lane < nw) ? ws2[lane] : 0.f;
        #pragma unroll
        for (int o = 16; o; o >>= 1){
            s  += __shfl_down_sync(0xffffffffu, s,  o);
            s2 += __shfl_down_sync(0xffffffffu, s2, o);
        }
        if (lane == 0){ atomicAdd(&g_sum, (double)s); atomicAdd(&g_sumsq, (double)s2); }
    }
}

__global__ void k_finalize(int E){
    double mean = g_sum / (double)E;
    double var  = (g_sumsq - g_sum*g_sum/(double)E) / (double)(E - 1);
    g_mean = (float)mean;
    g_istd = (float)(1.0 / sqrt(var));
}

// ---------------- KB: per-node projections YA/YB ----------------
__global__ void k_proj(const float* __restrict__ x, const float* __restrict__ W1,
                       const float* __restrict__ b1){
    __shared__ float sW[64*32];
    __shared__ float sb[32];
    for (int k = threadIdx.x; k < 64*32; k += blockDim.x) sW[k] = W1[k];
    if (threadIdx.x < 32) sb[threadIdx.x] = b1[threadIdx.x];
    __syncthreads();
    int id = blockIdx.x*blockDim.x + threadIdx.x;
    if (id >= BN) return;
    const float* xr = x + (size_t)id*FIN;
    float accA[32], accB[32];
    #pragma unroll
    for (int j = 0; j < 32; j++){ accA[j] = 0.f; accB[j] = sb[j]; }
    #pragma unroll 4
    for (int i = 0; i < 32; i++){
        float xv = __ldg(xr + i);
        #pragma unroll
        for (int j = 0; j < 32; j++){
            accA[j] = fmaf(xv, sW[i*32 + j],        accA[j]);
            accB[j] = fmaf(xv, sW[(32 + i)*32 + j], accB[j]);
        }
    }
    float* pa = g_YA + (size_t)id*32;
    float* pb = g_YB + (size_t)id*32;
    #pragma unroll
    for (int j = 0; j < 32; j++){ pa[j] = accA[j]; pb[j] = accB[j]; }
}

// ---------------- KD: edge MLP + vector-red scatter ----------------
__global__ __launch_bounds__(BD) void k_edge(
    const int* __restrict__ ei32, const float* __restrict__ eattr,
    const float* __restrict__ W1, const float* __restrict__ W2,
    const float* __restrict__ b2, int E)
{
    __shared__ float4 sA[BD*9];               // row stride 9 float4: LDS.128 conflict-free
    __shared__ float4 sB[BD*9];
    __shared__ __align__(16) float sW2[32*32];  // 32x30 padded to 32x32
    __shared__ __align__(16) float sw1c[32];
    __shared__ __align__(16) float sb2[32];
    __shared__ int sIA[BD], sIB[BD];

    int tid = threadIdx.x;
    for (int k = tid; k < 32*32; k += BD){
        int i = k >> 5, j = k & 31;
        sW2[k] = (j < H2) ? W2[i*H2 + j] : 0.f;
    }
    if (tid < 32){
        sw1c[tid] = W1[64*32 + tid];
        sb2[tid]  = (tid < H2) ? b2[tid] : 0.f;
    }

    long long item  = (long long)blockIdx.x*BD + tid;
    bool active = item < 4LL*E;
    int e = active ? (int)(item >> 2) : 0;
    int b = (int)(item & 3);
    int is64 = g_is64;
    int src, tgt;
    if (is64){ src = ei32[2*(size_t)e]; tgt = ei32[2*((size_t)E + e)]; }
    else     { src = ei32[e];           tgt = ei32[E + e]; }
    float ea = active ? (eattr[e] - g_mean) * g_istd : 0.f;
    int ia = b*NN + src;                     // row for src (subtract side)
    int ib = b*NN + tgt;                     // row for tgt (add side)
    sIA[tid] = ia;
    sIB[tid] = ib;
    __syncthreads();

    // Coalesced gather: 8 consecutive threads fetch one 128B row.
    const float4* ya4 = (const float4*)g_YA;
    const float4* yb4 = (const float4*)g_YB;
    #pragma unroll
    for (int k = tid; k < BD*8; k += BD){
        int row = k >> 3, q = k & 7;
        sA[row*9 + q] = ya4[(size_t)sIA[row]*8 + q];
        sB[row*9 + q] = yb4[(size_t)sIB[row]*8 + q];
    }
    __syncthreads();

    // Layer 1 (precomputed): h1 = sigmoid(YA[src] + YB[tgt] + ea*w1c)
    float h1[32];
    const float4* w1c4 = (const float4*)sw1c;
    #pragma unroll
    for (int q = 0; q < 8; q++){
        float4 a = sA[tid*9 + q];
        float4 t = sB[tid*9 + q];
        float4 w = w1c4[q];
        h1[4*q+0] = sigmoidf(fmaf(ea, w.x, a.x + t.x));
        h1[4*q+1] = sigmoidf(fmaf(ea, w.y, a.y + t.y));
        h1[4*q+2] = sigmoidf(fmaf(ea, w.z, a.z + t.z));
        h1[4*q+3] = sigmoidf(fmaf(ea, w.w, a.w + t.w));
    }

    // Layer 2: h2 = sigmoid(h1 @ W2 + b2), padded to 32 (pad lanes stay 0)
    float h2[32];
    #pragma unroll
    for (int j = 0; j < 32; j++) h2[j] = sb2[j];
    #pragma unroll
    for (int i = 0; i < 32; i++){
        float hv = h1[i];
        const float4* wr = (const float4*)(sW2 + i*32);
        #pragma unroll
        for (int q = 0; q < 8; q++){
            float4 w = wr[q];
            h2[4*q+0] = fmaf(hv, w.x, h2[4*q+0]);
            h2[4*q+1] = fmaf(hv, w.y, h2[4*q+1]);
            h2[4*q+2] = fmaf(hv, w.z, h2[4*q+2]);
            h2[4*q+3] = fmaf(hv, w.w, h2[4*q+3]);
        }
    }
    #pragma unroll
    for (int j = 0; j < H2; j++) h2[j] = sigmoidf(h2[j]);
    h2[30] = 0.f; h2[31] = 0.f;

    if (active){
        float* pt = g_SC + (size_t)ib*32;
        float* ps = g_SC + (size_t)ia*32;
        #pragma unroll
        for (int q = 0; q < 8; q++){
            red_add_v4(pt + 4*q,  h2[4*q],  h2[4*q+1],  h2[4*q+2],  h2[4*q+3]);
            red_add_v4(ps + 4*q, -h2[4*q], -h2[4*q+1], -h2[4*q+2], -h2[4*q+3]);
        }
    }
}

// ---------------- KE: out = sigmoid(SC @ W3 + b3) ----------------
__global__ void k_out(float* __restrict__ out, const float* __restrict__ W3,
                      const float* __restrict__ b3){
    __shared__ float sW[30*32];
    __shared__ float sb[32];
    for (int k = threadIdx.x; k < 30*32; k += blockDim.x) sW[k] = W3[k];
    if (threadIdx.x < 32) sb[threadIdx.x] = b3[threadIdx.x];
    __syncthreads();
    int id = blockIdx.x*blockDim.x + threadIdx.x;
    if (id >= BN) return;
    const float* sr = g_SC + (size_t)id*32;
    float acc[32];
    #pragma unroll
    for (int j = 0; j < 32; j++) acc[j] = sb[j];
    #pragma unroll 2
    for (int k = 0; k < 30; k++){
        float sv = sr[k];
        #pragma unroll
        for (int j = 0; j < 32; j++) acc[j] = fmaf(sv, sW[k*32 + j], acc[j]);
    }
    float* po = out + (size_t)id*32;
    #pragma unroll
    for (int j = 0; j < 32; j++) po[j] = sigmoidf(acc[j]);
}

extern "C" void kernel_launch(void* const* d_in, const int* in_sizes, int n_in,
                              void* d_out, int out_size){
    const float* x     = (const float*)d_in[0];
    const int*   ei32  = (const int*)d_in[1];    // int32 view; dtype probed on-device
    const float* eattr = (const float*)d_in[2];
    const float* W1    = (const float*)d_in[3];
    const float* b1    = (const float*)d_in[4];
    const float* W2    = (const float*)d_in[5];
    const float* b2    = (const float*)d_in[6];
    const float* W3    = (const float*)d_in[7];
    const float* b3    = (const float*)d_in[8];
    int E = in_sizes[1] / 2;

    k_zero<<<1024, 256>>>(ei32);
    k_stats<<<512, 256>>>(eattr, E);
    k_finalize<<<1, 1>>>(E);
    k_proj<<<(BN + 255)/256, 256>>>(x, W1, b1);
    long long items = 4LL * E;
    int blocks = (int)((items + BD - 1) / BD);
    k_edge<<<blocks, BD>>>(ei32, eattr, W1, W2, b2, E);
    k_out<<<(BN + 255)/256, 256>>>((float*)d_out, W3, b3);
}